// round 12
// baseline (speedup 1.0000x reference)
#include <cuda_runtime.h>
#include <cuda_fp16.h>
#include <math.h>
#include <stdint.h>

#define N 8192
#define D 1024
#define BM 128
#define BN 256
#define NTX (N / BN)         // 32 col tiles
#define NTY (N / BM)         // 64 row tiles
#define CHB 64               // bytes (=fp8 elems) of K per chunk
#define NCHUNK (D / CHB)     // 16
#define ROWB 80              // padded smem row stride (64B data + 16B pad)
#define A_BYTES (BM * ROWB)            // 10240
#define STAGE_BYTES ((BM + BN) * ROWB) // 30720
#define DSMEM_BYTES (4 * STAGE_BYTES)  // 122880
#define QSCALE 64.0f

// ---------------------------------------------------------------------------
// Device scratch
// ---------------------------------------------------------------------------
__device__ uint8_t g_A8[N * D];
__device__ uint8_t g_B8[N * D];
__device__ float4 g_rowP[NTX * N];   // (M, S, S2, SX) per [tile][row]
__device__ float4 g_colP[NTY * N];
__device__ float g_diag[N];     // exact fp32 logit (r,r)
__device__ float g_offx1[N];    // exact fp32 logit (r,r^1)
__device__ float g_offx2[N];    // exact fp32 logit (r,r^2)
__device__ float g_diag8[N];    // fp8-path logit (r,r)
__device__ float g_off81[N];    // fp8-path logit (r,r^1)
__device__ float g_off82[N];    // fp8-path logit (r,r^2)
__device__ float g_TA, g_TB;    // sum v*eps per matrix (Sheppard regression)
__device__ float g_logm1;       // log E[exp(noise)]
__device__ float g_varfac;      // (m2 - m1^2) / (2 m1^2)
__device__ float g_beta;        // multiplicative logit inflation
__device__ double g_acc;

// ---------------------------------------------------------------------------
// Portable PTX helpers
// ---------------------------------------------------------------------------
__device__ __forceinline__ uint32_t smem_u32(const void* p) {
    uint32_t a;
    asm("{ .reg .u64 t; cvta.to.shared.u64 t, %1; cvt.u32.u64 %0, t; }" : "=r"(a) : "l"(p));
    return a;
}

#define CP_ASYNC16(sa, gp) \
    asm volatile("cp.async.cg.shared.global [%0], [%1], 16;" :: "r"((uint32_t)(sa)), "l"(gp) : "memory")
#define CP_COMMIT() asm volatile("cp.async.commit_group;" ::: "memory")
#define CP_WAIT2()  asm volatile("cp.async.wait_group 2;" ::: "memory")

__device__ __forceinline__ void ldsm_x4(uint32_t* r, uint32_t addr) {
    asm volatile("ldmatrix.sync.aligned.m8n8.x4.shared.b16 {%0,%1,%2,%3}, [%4];"
                 : "=r"(r[0]), "=r"(r[1]), "=r"(r[2]), "=r"(r[3]) : "r"(addr));
}

__device__ __forceinline__ void mma_fp8(float* d, const uint32_t* a, uint32_t b0, uint32_t b1) {
    asm volatile(
        "mma.sync.aligned.m16n8k32.row.col.f32.e4m3.e4m3.f32 "
        "{%0,%1,%2,%3}, {%4,%5,%6,%7}, {%8,%9}, {%0,%1,%2,%3};"
        : "+f"(d[0]), "+f"(d[1]), "+f"(d[2]), "+f"(d[3])
        : "r"(a[0]), "r"(a[1]), "r"(a[2]), "r"(a[3]), "r"(b0), "r"(b1));
}

__device__ __forceinline__ uint16_t cvt_e4m3x2(float hi, float lo) {
    uint16_t p;
    asm("cvt.rn.satfinite.e4m3x2.f32 %0, %1, %2;" : "=h"(p) : "f"(hi), "f"(lo));
    return p;
}

// e4m3x2 (packed in b16) -> two fp32 (caller divides by QSCALE)
__device__ __forceinline__ float2 dequant_e4m3x2(uint16_t p) {
    uint32_t h2;
    asm("cvt.rn.f16x2.e4m3x2 %0, %1;" : "=r"(h2) : "h"(p));
    __half2 h = *reinterpret_cast<__half2*>(&h2);
    return __half22float2(h);
}

// ---------------------------------------------------------------------------
__global__ void init_kernel() { g_acc = 0.0; g_TA = 0.0f; g_TB = 0.0f; }

// fp32 -> e4m3, fused with exact fp32 calibration dots (r,r),(r,r^1),(r,r^2)
// and Sheppard regression accumulators T = sum v*(dequant(v)-v).
__global__ void __launch_bounds__(256)
convert_diag_kernel(const float* __restrict__ A, const float* __restrict__ B,
                    const float* __restrict__ scale_p) {
    __shared__ float s_r0[8], s_r1[8], s_r2[8], s_ta[8], s_tb[8];
    const int row = blockIdx.x;
    const int tid = threadIdx.x;
    const size_t base = (size_t)row * D + tid * 4;

    float4 a  = *(const float4*)(A + base);
    float4 b  = *(const float4*)(B + base);
    float4 b1 = *(const float4*)(B + (size_t)(row ^ 1) * D + tid * 4);
    float4 b2 = *(const float4*)(B + (size_t)(row ^ 2) * D + tid * 4);

    uint16_t pa0 = cvt_e4m3x2(a.y * QSCALE, a.x * QSCALE);
    uint16_t pa1 = cvt_e4m3x2(a.w * QSCALE, a.z * QSCALE);
    uint16_t pb0 = cvt_e4m3x2(b.y * QSCALE, b.x * QSCALE);
    uint16_t pb1 = cvt_e4m3x2(b.w * QSCALE, b.z * QSCALE);
    *(uint32_t*)(g_A8 + base) = (uint32_t)pa0 | ((uint32_t)pa1 << 16);
    *(uint32_t*)(g_B8 + base) = (uint32_t)pb0 | ((uint32_t)pb1 << 16);

    const float inv = 1.0f / QSCALE;
    float2 da0 = dequant_e4m3x2(pa0), da1 = dequant_e4m3x2(pa1);
    float2 db0 = dequant_e4m3x2(pb0), db1 = dequant_e4m3x2(pb1);
    float ta = a.x * (da0.x * inv - a.x) + a.y * (da0.y * inv - a.y)
             + a.z * (da1.x * inv - a.z) + a.w * (da1.y * inv - a.w);
    float tb = b.x * (db0.x * inv - b.x) + b.y * (db0.y * inv - b.y)
             + b.z * (db1.x * inv - b.z) + b.w * (db1.y * inv - b.w);

    float s0 = a.x * b.x  + a.y * b.y  + a.z * b.z  + a.w * b.w;
    float s1 = a.x * b1.x + a.y * b1.y + a.z * b1.z + a.w * b1.w;
    float s2 = a.x * b2.x + a.y * b2.y + a.z * b2.z + a.w * b2.w;
#pragma unroll
    for (int off = 16; off > 0; off >>= 1) {
        s0 += __shfl_xor_sync(0xffffffffu, s0, off);
        s1 += __shfl_xor_sync(0xffffffffu, s1, off);
        s2 += __shfl_xor_sync(0xffffffffu, s2, off);
        ta += __shfl_xor_sync(0xffffffffu, ta, off);
        tb += __shfl_xor_sync(0xffffffffu, tb, off);
    }
    if ((tid & 31) == 0) {
        int w = tid >> 5;
        s_r0[w] = s0; s_r1[w] = s1; s_r2[w] = s2; s_ta[w] = ta; s_tb[w] = tb;
    }
    __syncthreads();
    if (tid == 0) {
        float t0 = 0, t1 = 0, t2 = 0, tta = 0, ttb = 0;
#pragma unroll
        for (int w = 0; w < 8; w++) {
            t0 += s_r0[w]; t1 += s_r1[w]; t2 += s_r2[w];
            tta += s_ta[w]; ttb += s_tb[w];
        }
        float sc = __ldg(scale_p);
        g_diag[row]  = sc * t0;
        g_offx1[row] = sc * t1;
        g_offx2[row] = sc * t2;
        atomicAdd(&g_TA, tta);
        atomicAdd(&g_TB, ttb);
    }
}

// ---------------------------------------------------------------------------
// 128x256 tile e4m3 mma.sync GEMM + fused LSE partials (S, S2, SX).
// ---------------------------------------------------------------------------
__device__ __forceinline__ void prefetch_chunk(const uint8_t* Ag, const uint8_t* Bg,
                                               uint32_t sbase, int tid, int c) {
    if (c < NCHUNK) {
        uint32_t st = sbase + (uint32_t)(c & 3) * STAGE_BYTES;
        int k0 = c * CHB;
#pragma unroll
        for (int j = 0; j < 6; j++) {
            int idx = tid + j * 256;
            if (idx < 512) {
                int r = idx >> 2, g = idx & 3;
                CP_ASYNC16(st + r * ROWB + g * 16, Ag + (size_t)r * D + k0 + g * 16);
            } else {
                int e = idx - 512;
                int r = e >> 2, g = e & 3;
                CP_ASYNC16(st + A_BYTES + r * ROWB + g * 16, Bg + (size_t)r * D + k0 + g * 16);
            }
        }
    }
    CP_COMMIT();
}

__global__ void __launch_bounds__(256, 1)
gemm_lse_mma(const float* __restrict__ scale_p) {
    extern __shared__ char dsm[];
    __shared__ float s_red[8];
    __shared__ float4 s_rows[4][128];
    __shared__ float4 s_cols[2][256];

    const int tid = threadIdx.x;
    const int wid = tid >> 5;
    const int lane = tid & 31;
    const int wm = wid & 1;
    const int wn = wid >> 1;
    const int bx = blockIdx.x;
    const int by = blockIdx.y;

    const uint32_t sbase = smem_u32(dsm);
    const uint8_t* Ag = g_A8 + (size_t)by * BM * D;
    const uint8_t* Bg = g_B8 + (size_t)bx * BN * D;

    float acc[4][8][4];
#pragma unroll
    for (int mt = 0; mt < 4; mt++)
#pragma unroll
        for (int nt = 0; nt < 8; nt++)
#pragma unroll
            for (int i = 0; i < 4; i++) acc[mt][nt][i] = 0.0f;

    const uint32_t lOff = (uint32_t)((lane & 15) * ROWB + (lane >> 4) * 16);
    const uint32_t aOff = sbase + lOff + (uint32_t)(wm * 64 * ROWB);
    const uint32_t bOff = sbase + A_BYTES + lOff + (uint32_t)(wn * 64 * ROWB);

    prefetch_chunk(Ag, Bg, sbase, tid, 0);
    prefetch_chunk(Ag, Bg, sbase, tid, 1);
    prefetch_chunk(Ag, Bg, sbase, tid, 2);

    for (int c = 0; c < NCHUNK; c++) {
        CP_WAIT2();
        __syncthreads();
        prefetch_chunk(Ag, Bg, sbase, tid, c + 3);

        const uint32_t stoff = (uint32_t)(c & 3) * STAGE_BYTES;
#pragma unroll
        for (int ks = 0; ks < 2; ks++) {
            uint32_t afr[4][4];
#pragma unroll
            for (int mt = 0; mt < 4; mt++)
                ldsm_x4(afr[mt], aOff + stoff + (uint32_t)(mt * 16 * ROWB + ks * 32));
            uint32_t bfr[4][4];
#pragma unroll
            for (int q = 0; q < 4; q++)
                ldsm_x4(bfr[q], bOff + stoff + (uint32_t)(q * 16 * ROWB + ks * 32));
#pragma unroll
            for (int mt = 0; mt < 4; mt++)
#pragma unroll
                for (int nt = 0; nt < 8; nt++)
                    mma_fp8(acc[mt][nt], afr[mt],
                            bfr[nt >> 1][nt & 1], bfr[nt >> 1][(nt & 1) + 2]);
        }
    }

    // ---- Fused epilogue ----
    const float scale = __ldg(scale_p) / (QSCALE * QSCALE);
#pragma unroll
    for (int mt = 0; mt < 4; mt++)
#pragma unroll
        for (int nt = 0; nt < 8; nt++)
#pragma unroll
            for (int i = 0; i < 4; i++) acc[mt][nt][i] *= scale;

    // Calibration extraction (diag block: bx == by>>1)
    if (bx == (by >> 1)) {
        const int cbase = (by & 1) << 7;
#pragma unroll
        for (int mt = 0; mt < 4; mt++)
#pragma unroll
            for (int nt = 0; nt < 8; nt++)
#pragma unroll
                for (int i = 0; i < 4; i++) {
                    int r_loc = wm * 64 + mt * 16 + ((i >> 1) << 3) + (lane >> 2);
                    int c_loc = wn * 64 + nt * 8 + ((lane & 3) << 1) + (i & 1);
                    if (c_loc == r_loc + cbase)
                        g_diag8[by * BM + r_loc] = acc[mt][nt][i];
                    if (c_loc == (r_loc ^ 1) + cbase)
                        g_off81[by * BM + r_loc] = acc[mt][nt][i];
                    if (c_loc == (r_loc ^ 2) + cbase)
                        g_off82[by * BM + r_loc] = acc[mt][nt][i];
                }
    }

    float m = -INFINITY;
#pragma unroll
    for (int mt = 0; mt < 4; mt++)
#pragma unroll
        for (int nt = 0; nt < 8; nt++)
#pragma unroll
            for (int i = 0; i < 4; i++) m = fmaxf(m, acc[mt][nt][i]);
#pragma unroll
    for (int off = 16; off > 0; off >>= 1)
        m = fmaxf(m, __shfl_xor_sync(0xffffffffu, m, off));
    if (lane == 0) s_red[wid] = m;
    __syncthreads();
    float Mt = s_red[0];
#pragma unroll
    for (int w = 1; w < 8; w++) Mt = fmaxf(Mt, s_red[w]);

    // u = x - Mt in acc; e = exp(u): S = sum e, S2 = sum e^2, SX = sum u*e.
    float eu[4][8][4];
#pragma unroll
    for (int mt = 0; mt < 4; mt++)
#pragma unroll
        for (int nt = 0; nt < 8; nt++)
#pragma unroll
            for (int i = 0; i < 4; i++) {
                acc[mt][nt][i] -= Mt;
                eu[mt][nt][i] = __expf(acc[mt][nt][i]);
            }

    // Row partials
#pragma unroll
    for (int mt = 0; mt < 4; mt++)
#pragma unroll
        for (int half = 0; half < 2; half++) {
            float rs = 0, r2 = 0, rx = 0;
#pragma unroll
            for (int nt = 0; nt < 8; nt++) {
                float e0 = eu[mt][nt][half * 2], e1 = eu[mt][nt][half * 2 + 1];
                float u0 = acc[mt][nt][half * 2], u1 = acc[mt][nt][half * 2 + 1];
                rs += e0 + e1;
                r2 += e0 * e0 + e1 * e1;
                rx += u0 * e0 + u1 * e1;
            }
#pragma unroll
            for (int off = 1; off <= 2; off <<= 1) {
                rs += __shfl_xor_sync(0xffffffffu, rs, off);
                r2 += __shfl_xor_sync(0xffffffffu, r2, off);
                rx += __shfl_xor_sync(0xffffffffu, rx, off);
            }
            if ((lane & 3) == 0)
                s_rows[wn][wm * 64 + mt * 16 + half * 8 + (lane >> 2)] =
                    make_float4(Mt, rs, r2, rx);
        }

    // Col partials
#pragma unroll
    for (int nt = 0; nt < 8; nt++)
#pragma unroll
        for (int cc = 0; cc < 2; cc++) {
            float cs = 0, c2 = 0, cx = 0;
#pragma unroll
            for (int mt = 0; mt < 4; mt++) {
                float e0 = eu[mt][nt][cc], e1 = eu[mt][nt][cc + 2];
                float u0 = acc[mt][nt][cc], u1 = acc[mt][nt][cc + 2];
                cs += e0 + e1;
                c2 += e0 * e0 + e1 * e1;
                cx += u0 * e0 + u1 * e1;
            }
#pragma unroll
            for (int off = 4; off <= 16; off <<= 1) {
                cs += __shfl_xor_sync(0xffffffffu, cs, off);
                c2 += __shfl_xor_sync(0xffffffffu, c2, off);
                cx += __shfl_xor_sync(0xffffffffu, cx, off);
            }
            if (lane < 4)
                s_cols[wm][wn * 64 + nt * 8 + (lane & 3) * 2 + cc] =
                    make_float4(Mt, cs, c2, cx);
        }
    __syncthreads();

    if (tid < 128) {
        float4 p0 = s_rows[0][tid], p1 = s_rows[1][tid], p2 = s_rows[2][tid], p3 = s_rows[3][tid];
        g_rowP[(size_t)bx * N + by * BM + tid] =
            make_float4(Mt, p0.y + p1.y + p2.y + p3.y,
                            p0.z + p1.z + p2.z + p3.z,
                            p0.w + p1.w + p2.w + p3.w);
    }
    {
        float4 p0 = s_cols[0][tid], p1 = s_cols[1][tid];
        g_colP[(size_t)by * N + bx * BN + tid] =
            make_float4(Mt, p0.y + p1.y, p0.z + p1.z, p0.w + p1.w);
    }
}

// ---------------------------------------------------------------------------
// Stats: noise moments from calibration pairs + Sheppard beta.
// ---------------------------------------------------------------------------
__global__ void __launch_bounds__(256)
stats_kernel() {
    __shared__ float sm1[8], sm2[8];
    const int tid = threadIdx.x;
    float a1 = 0, a2 = 0;
    for (int k = tid; k < N; k += 256) {
        float d0 = g_diag8[k] - g_diag[k];
        float d1 = g_off81[k] - g_offx1[k];
        float d2 = g_off82[k] - g_offx2[k];
        float e0 = __expf(d0), e1 = __expf(d1), e2 = __expf(d2);
        a1 += e0 + e1 + e2;
        a2 += e0 * e0 + e1 * e1 + e2 * e2;
    }
#pragma unroll
    for (int off = 16; off > 0; off >>= 1) {
        a1 += __shfl_xor_sync(0xffffffffu, a1, off);
        a2 += __shfl_xor_sync(0xffffffffu, a2, off);
    }
    if ((tid & 31) == 0) { sm1[tid >> 5] = a1; sm2[tid >> 5] = a2; }
    __syncthreads();
    if (tid == 0) {
        float t1 = 0, t2 = 0;
#pragma unroll
        for (int w = 0; w < 8; w++) { t1 += sm1[w]; t2 += sm2[w]; }
        float m1 = t1 / (3.0f * N);
        float m2 = t2 / (3.0f * N);
        g_logm1 = logf(m1);
        g_varfac = (m2 - m1 * m1) / (2.0f * m1 * m1);
        // beta: per-element regression E[v*eps]/E[v^2]; rows unit-norm -> sum v^2 = N
        g_beta = (g_TA + g_TB) / (float)N;
    }
}

// ---------------------------------------------------------------------------
// Combine partials -> corrected lse, subtract diag, reduce.
// Seed online state from tile 0 (NOT -inf) to avoid inf*0 = NaN in SX merge.
// ---------------------------------------------------------------------------
__global__ void reduce_kernel() {
    const bool rowdir = blockIdx.x < 32;
    const int i = (rowdir ? blockIdx.x : blockIdx.x - 32) * 256 + threadIdx.x;
    const int nt = rowdir ? NTX : NTY;
    const float4* P = rowdir ? g_rowP : g_colP;

    float4 p0 = P[i];
    float m = p0.x, s = p0.y, s2 = p0.z, sx = p0.w;
    for (int t = 1; t < nt; t++) {
        float4 p = P[(size_t)t * N + i];
        float nm = fmaxf(m, p.x);
        float e1 = __expf(m - nm), e2 = __expf(p.x - nm);
        sx = (sx + (m - nm) * s) * e1 + (p.w + (p.x - nm) * p.y) * e2;
        s  = s * e1 + p.y * e2;
        s2 = s2 * e1 * e1 + p.z * e2 * e2;
        m = nm;
    }
    float sump2 = s2 / (s * s);
    float epx = m + sx / s;            // E_p[x] for this row/col
    float lse = m + logf(s) - g_logm1 + g_varfac * sump2 - g_beta * epx;
    float v = lse - g_diag[i];

    __shared__ float sm[256];
    sm[threadIdx.x] = v;
    __syncthreads();
    for (int off = 128; off > 0; off >>= 1) {
        if (threadIdx.x < off) sm[threadIdx.x] += sm[threadIdx.x + off];
        __syncthreads();
    }
    if (threadIdx.x == 0) atomicAdd(&g_acc, (double)sm[0]);
}

__global__ void final_kernel(float* out) {
    out[0] = (float)(g_acc / (2.0 * (double)N));
}

// ---------------------------------------------------------------------------
extern "C" void kernel_launch(void* const* d_in, const int* in_sizes, int n_in,
                              void* d_out, int out_size) {
    const float* img   = (const float*)d_in[0];
    const float* txt   = (const float*)d_in[1];
    const float* scale = (const float*)d_in[2];
    float* out = (float*)d_out;

    cudaFuncSetAttribute(gemm_lse_mma, cudaFuncAttributeMaxDynamicSharedMemorySize, DSMEM_BYTES);

    init_kernel<<<1, 1>>>();
    convert_diag_kernel<<<N, 256>>>(img, txt, scale);

    dim3 grid(NTX, NTY);  // 32 x 64
    gemm_lse_mma<<<grid, 256, DSMEM_BYTES>>>(scale);

    stats_kernel<<<1, 256>>>();
    reduce_kernel<<<64, 256>>>();
    final_kernel<<<1, 1>>>(out);
}

// round 13
// speedup vs baseline: 1.0864x; 1.0864x over previous
#include <cuda_runtime.h>
#include <cuda_fp16.h>
#include <math.h>
#include <stdint.h>

#define N 8192
#define D 1024
#define BM 128
#define BN 256
#define NTX (N / BN)         // 32 col tiles
#define NTY (N / BM)         // 64 row tiles
#define CHB 64               // bytes (=fp8 elems) of K per chunk
#define NCHUNK (D / CHB)     // 16
#define ROWB 80              // padded smem row stride (64B data + 16B pad)
#define A_BYTES (BM * ROWB)            // 10240
#define STAGE_BYTES ((BM + BN) * ROWB) // 30720
#define DSMEM_BYTES (4 * STAGE_BYTES)  // 122880
#define QSCALE 64.0f

// ---------------------------------------------------------------------------
// Device scratch
// ---------------------------------------------------------------------------
__device__ uint8_t g_A8[N * D];
__device__ uint8_t g_B8[N * D];
__device__ float2 g_rowP[NTX * N];   // (M, S) per [tile][row]
__device__ float2 g_colP[NTY * N];
__device__ float g_diag[N];     // exact fp32 logit (r,r)
__device__ float g_offx1[N];    // exact fp32 logit (r,r^1)
__device__ float g_diag8[N];    // fp8-path logit (r,r)   (beta-prescaled)
__device__ float g_off81[N];    // fp8-path logit (r,r^1) (beta-prescaled)
__device__ float g_TA, g_TB;    // sum v*eps per matrix (Sheppard regression)
__device__ float g_beta;        // multiplicative logit inflation
__device__ float g_m1sum;       // sum of exp(delta) over calibration pairs
__device__ double g_acc;

// ---------------------------------------------------------------------------
// Portable PTX helpers (sm_80/sm_89 baseline -> OK under compute_103)
// ---------------------------------------------------------------------------
__device__ __forceinline__ uint32_t smem_u32(const void* p) {
    uint32_t a;
    asm("{ .reg .u64 t; cvta.to.shared.u64 t, %1; cvt.u32.u64 %0, t; }" : "=r"(a) : "l"(p));
    return a;
}

#define CP_ASYNC16(sa, gp) \
    asm volatile("cp.async.cg.shared.global [%0], [%1], 16;" :: "r"((uint32_t)(sa)), "l"(gp) : "memory")
#define CP_COMMIT() asm volatile("cp.async.commit_group;" ::: "memory")
#define CP_WAIT2()  asm volatile("cp.async.wait_group 2;" ::: "memory")

__device__ __forceinline__ void ldsm_x4(uint32_t* r, uint32_t addr) {
    asm volatile("ldmatrix.sync.aligned.m8n8.x4.shared.b16 {%0,%1,%2,%3}, [%4];"
                 : "=r"(r[0]), "=r"(r[1]), "=r"(r[2]), "=r"(r[3]) : "r"(addr));
}

__device__ __forceinline__ void mma_fp8(float* d, const uint32_t* a, uint32_t b0, uint32_t b1) {
    asm volatile(
        "mma.sync.aligned.m16n8k32.row.col.f32.e4m3.e4m3.f32 "
        "{%0,%1,%2,%3}, {%4,%5,%6,%7}, {%8,%9}, {%0,%1,%2,%3};"
        : "+f"(d[0]), "+f"(d[1]), "+f"(d[2]), "+f"(d[3])
        : "r"(a[0]), "r"(a[1]), "r"(a[2]), "r"(a[3]), "r"(b0), "r"(b1));
}

__device__ __forceinline__ uint16_t cvt_e4m3x2(float hi, float lo) {
    uint16_t p;
    asm("cvt.rn.satfinite.e4m3x2.f32 %0, %1, %2;" : "=h"(p) : "f"(hi), "f"(lo));
    return p;
}

// e4m3x2 (packed in b16) -> two fp32 (caller divides by QSCALE)
__device__ __forceinline__ float2 dequant_e4m3x2(uint16_t p) {
    uint32_t h2;
    asm("cvt.rn.f16x2.e4m3x2 %0, %1;" : "=r"(h2) : "h"(p));
    __half2 h = *reinterpret_cast<__half2*>(&h2);
    return __half22float2(h);
}

// ---------------------------------------------------------------------------
__global__ void init_kernel() {
    g_acc = 0.0; g_TA = 0.0f; g_TB = 0.0f; g_m1sum = 0.0f;
}

// fp32 -> e4m3, fused with exact fp32 calibration dots (r,r),(r,r^1)
// and Sheppard regression accumulators T = sum v*(dequant(v)-v).
__global__ void __launch_bounds__(256)
convert_diag_kernel(const float* __restrict__ A, const float* __restrict__ B,
                    const float* __restrict__ scale_p) {
    __shared__ float s_r0[8], s_r1[8], s_ta[8], s_tb[8];
    const int row = blockIdx.x;
    const int tid = threadIdx.x;
    const size_t base = (size_t)row * D + tid * 4;

    float4 a  = *(const float4*)(A + base);
    float4 b  = *(const float4*)(B + base);
    float4 b1 = *(const float4*)(B + (size_t)(row ^ 1) * D + tid * 4);

    uint16_t pa0 = cvt_e4m3x2(a.y * QSCALE, a.x * QSCALE);
    uint16_t pa1 = cvt_e4m3x2(a.w * QSCALE, a.z * QSCALE);
    uint16_t pb0 = cvt_e4m3x2(b.y * QSCALE, b.x * QSCALE);
    uint16_t pb1 = cvt_e4m3x2(b.w * QSCALE, b.z * QSCALE);
    *(uint32_t*)(g_A8 + base) = (uint32_t)pa0 | ((uint32_t)pa1 << 16);
    *(uint32_t*)(g_B8 + base) = (uint32_t)pb0 | ((uint32_t)pb1 << 16);

    const float inv = 1.0f / QSCALE;
    float2 da0 = dequant_e4m3x2(pa0), da1 = dequant_e4m3x2(pa1);
    float2 db0 = dequant_e4m3x2(pb0), db1 = dequant_e4m3x2(pb1);
    float ta = a.x * (da0.x * inv - a.x) + a.y * (da0.y * inv - a.y)
             + a.z * (da1.x * inv - a.z) + a.w * (da1.y * inv - a.w);
    float tb = b.x * (db0.x * inv - b.x) + b.y * (db0.y * inv - b.y)
             + b.z * (db1.x * inv - b.z) + b.w * (db1.y * inv - b.w);

    float s0 = a.x * b.x  + a.y * b.y  + a.z * b.z  + a.w * b.w;
    float s1 = a.x * b1.x + a.y * b1.y + a.z * b1.z + a.w * b1.w;
#pragma unroll
    for (int off = 16; off > 0; off >>= 1) {
        s0 += __shfl_xor_sync(0xffffffffu, s0, off);
        s1 += __shfl_xor_sync(0xffffffffu, s1, off);
        ta += __shfl_xor_sync(0xffffffffu, ta, off);
        tb += __shfl_xor_sync(0xffffffffu, tb, off);
    }
    if ((tid & 31) == 0) {
        int w = tid >> 5;
        s_r0[w] = s0; s_r1[w] = s1; s_ta[w] = ta; s_tb[w] = tb;
    }
    __syncthreads();
    if (tid == 0) {
        float t0 = 0, t1 = 0, tta = 0, ttb = 0;
#pragma unroll
        for (int w = 0; w < 8; w++) {
            t0 += s_r0[w]; t1 += s_r1[w]; tta += s_ta[w]; ttb += s_tb[w];
        }
        float sc = __ldg(scale_p);
        g_diag[row]  = sc * t0;
        g_offx1[row] = sc * t1;
        atomicAdd(&g_TA, tta);
        atomicAdd(&g_TB, ttb);
    }
}

// beta from Sheppard regression; rows unit-norm -> sum v^2 per matrix = N
__global__ void beta_kernel() {
    g_beta = (g_TA + g_TB) / (float)N;
}

// ---------------------------------------------------------------------------
// 128x256 tile e4m3 mma.sync GEMM + fused LSE partials. Logits pre-scaled
// by (1 - beta) to cancel the multiplicative fp8 quantization channel.
// ---------------------------------------------------------------------------
__device__ __forceinline__ void prefetch_chunk(const uint8_t* Ag, const uint8_t* Bg,
                                               uint32_t sbase, int tid, int c) {
    if (c < NCHUNK) {
        uint32_t st = sbase + (uint32_t)(c & 3) * STAGE_BYTES;
        int k0 = c * CHB;
#pragma unroll
        for (int j = 0; j < 6; j++) {
            int idx = tid + j * 256;
            if (idx < 512) {
                int r = idx >> 2, g = idx & 3;
                CP_ASYNC16(st + r * ROWB + g * 16, Ag + (size_t)r * D + k0 + g * 16);
            } else {
                int e = idx - 512;
                int r = e >> 2, g = e & 3;
                CP_ASYNC16(st + A_BYTES + r * ROWB + g * 16, Bg + (size_t)r * D + k0 + g * 16);
            }
        }
    }
    CP_COMMIT();
}

__global__ void __launch_bounds__(256, 1)
gemm_lse_mma(const float* __restrict__ scale_p) {
    extern __shared__ char dsm[];
    __shared__ float s_red[8];
    __shared__ float s_rows[4][128];
    __shared__ float s_cols[2][256];

    const int tid = threadIdx.x;
    const int wid = tid >> 5;
    const int lane = tid & 31;
    const int wm = wid & 1;
    const int wn = wid >> 1;
    const int bx = blockIdx.x;
    const int by = blockIdx.y;

    const uint32_t sbase = smem_u32(dsm);
    const uint8_t* Ag = g_A8 + (size_t)by * BM * D;
    const uint8_t* Bg = g_B8 + (size_t)bx * BN * D;

    float acc[4][8][4];
#pragma unroll
    for (int mt = 0; mt < 4; mt++)
#pragma unroll
        for (int nt = 0; nt < 8; nt++)
#pragma unroll
            for (int i = 0; i < 4; i++) acc[mt][nt][i] = 0.0f;

    const uint32_t lOff = (uint32_t)((lane & 15) * ROWB + (lane >> 4) * 16);
    const uint32_t aOff = sbase + lOff + (uint32_t)(wm * 64 * ROWB);
    const uint32_t bOff = sbase + A_BYTES + lOff + (uint32_t)(wn * 64 * ROWB);

    prefetch_chunk(Ag, Bg, sbase, tid, 0);
    prefetch_chunk(Ag, Bg, sbase, tid, 1);
    prefetch_chunk(Ag, Bg, sbase, tid, 2);

    for (int c = 0; c < NCHUNK; c++) {
        CP_WAIT2();
        __syncthreads();
        prefetch_chunk(Ag, Bg, sbase, tid, c + 3);

        const uint32_t stoff = (uint32_t)(c & 3) * STAGE_BYTES;
#pragma unroll
        for (int ks = 0; ks < 2; ks++) {
            uint32_t afr[4][4];
#pragma unroll
            for (int mt = 0; mt < 4; mt++)
                ldsm_x4(afr[mt], aOff + stoff + (uint32_t)(mt * 16 * ROWB + ks * 32));
            uint32_t bfr[4][4];
#pragma unroll
            for (int q = 0; q < 4; q++)
                ldsm_x4(bfr[q], bOff + stoff + (uint32_t)(q * 16 * ROWB + ks * 32));
#pragma unroll
            for (int mt = 0; mt < 4; mt++)
#pragma unroll
                for (int nt = 0; nt < 8; nt++)
                    mma_fp8(acc[mt][nt], afr[mt],
                            bfr[nt >> 1][nt & 1], bfr[nt >> 1][(nt & 1) + 2]);
        }
    }

    // ---- Fused epilogue: logits = acc * scale * (1-beta) / QSCALE^2 ----
    const float scale = __ldg(scale_p) * (1.0f - g_beta) / (QSCALE * QSCALE);
#pragma unroll
    for (int mt = 0; mt < 4; mt++)
#pragma unroll
        for (int nt = 0; nt < 8; nt++)
#pragma unroll
            for (int i = 0; i < 4; i++) acc[mt][nt][i] *= scale;

    // Calibration extraction (diag block: bx == by>>1)
    if (bx == (by >> 1)) {
        const int cbase = (by & 1) << 7;
#pragma unroll
        for (int mt = 0; mt < 4; mt++)
#pragma unroll
            for (int nt = 0; nt < 8; nt++)
#pragma unroll
                for (int i = 0; i < 4; i++) {
                    int r_loc = wm * 64 + mt * 16 + ((i >> 1) << 3) + (lane >> 2);
                    int c_loc = wn * 64 + nt * 8 + ((lane & 3) << 1) + (i & 1);
                    if (c_loc == r_loc + cbase)
                        g_diag8[by * BM + r_loc] = acc[mt][nt][i];
                    if (c_loc == (r_loc ^ 1) + cbase)
                        g_off81[by * BM + r_loc] = acc[mt][nt][i];
                }
    }

    float m = -INFINITY;
#pragma unroll
    for (int mt = 0; mt < 4; mt++)
#pragma unroll
        for (int nt = 0; nt < 8; nt++)
#pragma unroll
            for (int i = 0; i < 4; i++) m = fmaxf(m, acc[mt][nt][i]);
#pragma unroll
    for (int off = 16; off > 0; off >>= 1)
        m = fmaxf(m, __shfl_xor_sync(0xffffffffu, m, off));
    if (lane == 0) s_red[wid] = m;
    __syncthreads();
    float Mt = s_red[0];
#pragma unroll
    for (int w = 1; w < 8; w++) Mt = fmaxf(Mt, s_red[w]);

#pragma unroll
    for (int mt = 0; mt < 4; mt++)
#pragma unroll
        for (int nt = 0; nt < 8; nt++)
#pragma unroll
            for (int i = 0; i < 4; i++)
                acc[mt][nt][i] = __expf(acc[mt][nt][i] - Mt);

    // Row partial sums. Accum layout: reg i: row (i>>1)*8+(lane>>2),
    // col (lane&3)*2+(i&1), within each 16x8 sub-tile.
#pragma unroll
    for (int mt = 0; mt < 4; mt++)
#pragma unroll
        for (int half = 0; half < 2; half++) {
            float rs = 0.0f;
#pragma unroll
            for (int nt = 0; nt < 8; nt++)
                rs += acc[mt][nt][half * 2] + acc[mt][nt][half * 2 + 1];
            rs += __shfl_xor_sync(0xffffffffu, rs, 1);
            rs += __shfl_xor_sync(0xffffffffu, rs, 2);
            if ((lane & 3) == 0)
                s_rows[wn][wm * 64 + mt * 16 + half * 8 + (lane >> 2)] = rs;
        }

    // Col partial sums
#pragma unroll
    for (int nt = 0; nt < 8; nt++)
#pragma unroll
        for (int cc = 0; cc < 2; cc++) {
            float cs = 0.0f;
#pragma unroll
            for (int mt = 0; mt < 4; mt++)
                cs += acc[mt][nt][cc] + acc[mt][nt][cc + 2];
            cs += __shfl_xor_sync(0xffffffffu, cs, 4);
            cs += __shfl_xor_sync(0xffffffffu, cs, 8);
            cs += __shfl_xor_sync(0xffffffffu, cs, 16);
            if (lane < 4)
                s_cols[wm][wn * 64 + nt * 8 + (lane & 3) * 2 + cc] = cs;
        }
    __syncthreads();

    if (tid < 128) {
        float rs = s_rows[0][tid] + s_rows[1][tid] + s_rows[2][tid] + s_rows[3][tid];
        g_rowP[(size_t)bx * N + by * BM + tid] = make_float2(Mt, rs);
    }
    {
        float cs = s_cols[0][tid] + s_cols[1][tid];
        g_colP[(size_t)by * N + bx * BN + tid] = make_float2(Mt, cs);
    }
}

// ---------------------------------------------------------------------------
// Stats: accumulate sum exp(delta) over 2N calibration pairs (32 blocks).
// ---------------------------------------------------------------------------
__global__ void __launch_bounds__(256)
stats_kernel() {
    __shared__ float sm[8];
    const int tid = threadIdx.x;
    const int k = blockIdx.x * 256 + tid;
    float d0 = g_diag8[k] - g_diag[k];
    float d1 = g_off81[k] - g_offx1[k];
    float a1 = __expf(d0) + __expf(d1);
#pragma unroll
    for (int off = 16; off > 0; off >>= 1)
        a1 += __shfl_xor_sync(0xffffffffu, a1, off);
    if ((tid & 31) == 0) sm[tid >> 5] = a1;
    __syncthreads();
    if (tid == 0) {
        float t = 0;
#pragma unroll
        for (int w = 0; w < 8; w++) t += sm[w];
        atomicAdd(&g_m1sum, t);
    }
}

// ---------------------------------------------------------------------------
// Combine partials -> bias-corrected lse, subtract diag, reduce.
// Blocks 0..31: rows (NTX tiles). Blocks 32..63: cols (NTY tiles).
// ---------------------------------------------------------------------------
__global__ void reduce_kernel() {
    const bool rowdir = blockIdx.x < 32;
    const int i = (rowdir ? blockIdx.x : blockIdx.x - 32) * 256 + threadIdx.x;
    const int nt = rowdir ? NTX : NTY;
    const float2* P = rowdir ? g_rowP : g_colP;

    const float logm1 = logf(g_m1sum / (2.0f * N));

    float m = -INFINITY, s = 0.0f;
    for (int t = 0; t < nt; t++) {
        float2 p = P[(size_t)t * N + i];
        float nm = fmaxf(m, p.x);
        s = s * __expf(m - nm) + p.y * __expf(p.x - nm);
        m = nm;
    }
    float lse = m + logf(s) - logm1;
    float v = lse - g_diag[i];

    __shared__ float sm[256];
    sm[threadIdx.x] = v;
    __syncthreads();
    for (int off = 128; off > 0; off >>= 1) {
        if (threadIdx.x < off) sm[threadIdx.x] += sm[threadIdx.x + off];
        __syncthreads();
    }
    if (threadIdx.x == 0) atomicAdd(&g_acc, (double)sm[0]);
}

__global__ void final_kernel(float* out) {
    out[0] = (float)(g_acc / (2.0 * (double)N));
}

// ---------------------------------------------------------------------------
extern "C" void kernel_launch(void* const* d_in, const int* in_sizes, int n_in,
                              void* d_out, int out_size) {
    const float* img   = (const float*)d_in[0];
    const float* txt   = (const float*)d_in[1];
    const float* scale = (const float*)d_in[2];
    float* out = (float*)d_out;

    cudaFuncSetAttribute(gemm_lse_mma, cudaFuncAttributeMaxDynamicSharedMemorySize, DSMEM_BYTES);

    init_kernel<<<1, 1>>>();
    convert_diag_kernel<<<N, 256>>>(img, txt, scale);
    beta_kernel<<<1, 1>>>();

    dim3 grid(NTX, NTY);  // 32 x 64
    gemm_lse_mma<<<grid, 256, DSMEM_BYTES>>>(scale);

    stats_kernel<<<32, 256>>>();
    reduce_kernel<<<64, 256>>>();
    final_kernel<<<1, 1>>>(out);
}

// round 14
// speedup vs baseline: 1.2211x; 1.1240x over previous
#include <cuda_runtime.h>
#include <cuda_fp16.h>
#include <math.h>
#include <stdint.h>

#define N 8192
#define D 1024
#define BM 128
#define BN 128
#define NT (N / 128)         // 64 tiles each direction
#define CHB 64               // fp8 elems of K per chunk (64B/row)
#define NCHUNK (D / CHB)     // 16
#define ROWB 80              // padded smem row stride (64B data + 16B pad)
#define A_BYTES (BM * ROWB)            // 10240
#define STAGE_BYTES (2 * BM * ROWB)    // 20480
#define DSMEM_BYTES (4 * STAGE_BYTES)  // 81920
#define QSCALE 64.0f

// ---------------------------------------------------------------------------
// Device scratch
// ---------------------------------------------------------------------------
__device__ uint8_t g_A8[N * D];
__device__ uint8_t g_B8[N * D];
__device__ float2 g_rowP[NT * N];   // (M, S) per [tile][row]
__device__ float2 g_colP[NT * N];
__device__ float g_diag[N];     // exact fp32 logit (r,r)
__device__ float g_offx1[N];    // exact fp32 logit (r,r^1)
__device__ float g_diag8[N];    // fp8-path logit (r,r)   (beta-prescaled)
__device__ float g_off81[N];    // fp8-path logit (r,r^1) (beta-prescaled)
__device__ float g_TA, g_TB;    // sum v*eps per matrix (Sheppard regression)
__device__ float g_beta;        // multiplicative logit inflation
__device__ float g_m1sum;       // sum exp(delta) over calibration pairs
__device__ double g_acc;

// ---------------------------------------------------------------------------
// Portable PTX helpers (sm_80/sm_89 baseline -> OK under compute_103)
// ---------------------------------------------------------------------------
__device__ __forceinline__ uint32_t smem_u32(const void* p) {
    uint32_t a;
    asm("{ .reg .u64 t; cvta.to.shared.u64 t, %1; cvt.u32.u64 %0, t; }" : "=r"(a) : "l"(p));
    return a;
}

#define CP_ASYNC16(sa, gp) \
    asm volatile("cp.async.cg.shared.global [%0], [%1], 16;" :: "r"((uint32_t)(sa)), "l"(gp) : "memory")
#define CP_COMMIT() asm volatile("cp.async.commit_group;" ::: "memory")
#define CP_WAIT2()  asm volatile("cp.async.wait_group 2;" ::: "memory")

__device__ __forceinline__ void ldsm_x4(uint32_t* r, uint32_t addr) {
    asm volatile("ldmatrix.sync.aligned.m8n8.x4.shared.b16 {%0,%1,%2,%3}, [%4];"
                 : "=r"(r[0]), "=r"(r[1]), "=r"(r[2]), "=r"(r[3]) : "r"(addr));
}

__device__ __forceinline__ void mma_fp8(float* d, const uint32_t* a, uint32_t b0, uint32_t b1) {
    asm volatile(
        "mma.sync.aligned.m16n8k32.row.col.f32.e4m3.e4m3.f32 "
        "{%0,%1,%2,%3}, {%4,%5,%6,%7}, {%8,%9}, {%0,%1,%2,%3};"
        : "+f"(d[0]), "+f"(d[1]), "+f"(d[2]), "+f"(d[3])
        : "r"(a[0]), "r"(a[1]), "r"(a[2]), "r"(a[3]), "r"(b0), "r"(b1));
}

__device__ __forceinline__ uint16_t cvt_e4m3x2(float hi, float lo) {
    uint16_t p;
    asm("cvt.rn.satfinite.e4m3x2.f32 %0, %1, %2;" : "=h"(p) : "f"(hi), "f"(lo));
    return p;
}

__device__ __forceinline__ float2 dequant_e4m3x2(uint16_t p) {
    uint32_t h2;
    asm("cvt.rn.f16x2.e4m3x2 %0, %1;" : "=r"(h2) : "h"(p));
    __half2 h = *reinterpret_cast<__half2*>(&h2);
    return __half22float2(h);
}

// ---------------------------------------------------------------------------
__global__ void init_kernel() {
    g_acc = 0.0; g_TA = 0.0f; g_TB = 0.0f; g_m1sum = 0.0f;
}

// fp32 -> e4m3, fused with exact fp32 calibration dots (r,r),(r,r^1)
// and Sheppard regression accumulators T = sum v*(dequant(v)-v).
__global__ void __launch_bounds__(256)
convert_diag_kernel(const float* __restrict__ A, const float* __restrict__ B,
                    const float* __restrict__ scale_p) {
    __shared__ float s_r0[8], s_r1[8], s_ta[8], s_tb[8];
    const int row = blockIdx.x;
    const int tid = threadIdx.x;
    const size_t base = (size_t)row * D + tid * 4;

    float4 a  = *(const float4*)(A + base);
    float4 b  = *(const float4*)(B + base);
    float4 b1 = *(const float4*)(B + (size_t)(row ^ 1) * D + tid * 4);

    uint16_t pa0 = cvt_e4m3x2(a.y * QSCALE, a.x * QSCALE);
    uint16_t pa1 = cvt_e4m3x2(a.w * QSCALE, a.z * QSCALE);
    uint16_t pb0 = cvt_e4m3x2(b.y * QSCALE, b.x * QSCALE);
    uint16_t pb1 = cvt_e4m3x2(b.w * QSCALE, b.z * QSCALE);
    *(uint32_t*)(g_A8 + base) = (uint32_t)pa0 | ((uint32_t)pa1 << 16);
    *(uint32_t*)(g_B8 + base) = (uint32_t)pb0 | ((uint32_t)pb1 << 16);

    const float inv = 1.0f / QSCALE;
    float2 da0 = dequant_e4m3x2(pa0), da1 = dequant_e4m3x2(pa1);
    float2 db0 = dequant_e4m3x2(pb0), db1 = dequant_e4m3x2(pb1);
    float ta = a.x * (da0.x * inv - a.x) + a.y * (da0.y * inv - a.y)
             + a.z * (da1.x * inv - a.z) + a.w * (da1.y * inv - a.w);
    float tb = b.x * (db0.x * inv - b.x) + b.y * (db0.y * inv - b.y)
             + b.z * (db1.x * inv - b.z) + b.w * (db1.y * inv - b.w);

    float s0 = a.x * b.x  + a.y * b.y  + a.z * b.z  + a.w * b.w;
    float s1 = a.x * b1.x + a.y * b1.y + a.z * b1.z + a.w * b1.w;
#pragma unroll
    for (int off = 16; off > 0; off >>= 1) {
        s0 += __shfl_xor_sync(0xffffffffu, s0, off);
        s1 += __shfl_xor_sync(0xffffffffu, s1, off);
        ta += __shfl_xor_sync(0xffffffffu, ta, off);
        tb += __shfl_xor_sync(0xffffffffu, tb, off);
    }
    if ((tid & 31) == 0) {
        int w = tid >> 5;
        s_r0[w] = s0; s_r1[w] = s1; s_ta[w] = ta; s_tb[w] = tb;
    }
    __syncthreads();
    if (tid == 0) {
        float t0 = 0, t1 = 0, tta = 0, ttb = 0;
#pragma unroll
        for (int w = 0; w < 8; w++) {
            t0 += s_r0[w]; t1 += s_r1[w]; tta += s_ta[w]; ttb += s_tb[w];
        }
        float sc = __ldg(scale_p);
        g_diag[row]  = sc * t0;
        g_offx1[row] = sc * t1;
        atomicAdd(&g_TA, tta);
        atomicAdd(&g_TB, ttb);
    }
}

// beta from Sheppard regression; rows unit-norm -> sum v^2 per matrix = N
__global__ void beta_kernel() {
    g_beta = (g_TA + g_TB) / (float)N;
}

// ---------------------------------------------------------------------------
// 128x128 tile e4m3 mma.sync GEMM + fused LSE partials. Warp tile 64x32,
// 2 CTAs/SM for issue-latency hiding. Logits pre-scaled by (1-beta).
// ---------------------------------------------------------------------------
__device__ __forceinline__ void prefetch_chunk(const uint8_t* Ag, const uint8_t* Bg,
                                               uint32_t sbase, int tid, int c) {
    if (c < NCHUNK) {
        uint32_t st = sbase + (uint32_t)(c & 3) * STAGE_BYTES;
        int k0 = c * CHB;
#pragma unroll
        for (int j = 0; j < 4; j++) {
            int idx = tid + j * 256;          // 0..1023
            if (idx < 512) {
                int r = idx >> 2, g = idx & 3;
                CP_ASYNC16(st + r * ROWB + g * 16, Ag + (size_t)r * D + k0 + g * 16);
            } else {
                int e = idx - 512;
                int r = e >> 2, g = e & 3;
                CP_ASYNC16(st + A_BYTES + r * ROWB + g * 16, Bg + (size_t)r * D + k0 + g * 16);
            }
        }
    }
    CP_COMMIT();
}

__global__ void __launch_bounds__(256, 2)
gemm_lse_mma(const float* __restrict__ scale_p) {
    extern __shared__ char dsm[];
    __shared__ float s_red[8];
    __shared__ float s_rows[4][128];
    __shared__ float s_cols[2][128];

    const int tid = threadIdx.x;
    const int wid = tid >> 5;
    const int lane = tid & 31;
    const int wm = wid & 1;    // M half (rows wm*64 .. +64)
    const int wn = wid >> 1;   // N quarter (cols wn*32 .. +32)
    const int bx = blockIdx.x;
    const int by = blockIdx.y;

    const uint32_t sbase = smem_u32(dsm);
    const uint8_t* Ag = g_A8 + (size_t)by * BM * D;
    const uint8_t* Bg = g_B8 + (size_t)bx * BN * D;

    float acc[4][4][4];
#pragma unroll
    for (int mt = 0; mt < 4; mt++)
#pragma unroll
        for (int nt = 0; nt < 4; nt++)
#pragma unroll
            for (int i = 0; i < 4; i++) acc[mt][nt][i] = 0.0f;

    const uint32_t lOff = (uint32_t)((lane & 15) * ROWB + (lane >> 4) * 16);
    const uint32_t aOff = sbase + lOff + (uint32_t)(wm * 64 * ROWB);
    const uint32_t bOff = sbase + A_BYTES + lOff + (uint32_t)(wn * 32 * ROWB);

    prefetch_chunk(Ag, Bg, sbase, tid, 0);
    prefetch_chunk(Ag, Bg, sbase, tid, 1);
    prefetch_chunk(Ag, Bg, sbase, tid, 2);

    for (int c = 0; c < NCHUNK; c++) {
        CP_WAIT2();            // chunk c resident
        __syncthreads();       // all warps done reading stage (c-1)&3
        prefetch_chunk(Ag, Bg, sbase, tid, c + 3);

        const uint32_t stoff = (uint32_t)(c & 3) * STAGE_BYTES;
#pragma unroll
        for (int ks = 0; ks < 2; ks++) {   // two k32 steps (32B each)
            uint32_t afr[4][4];
#pragma unroll
            for (int mt = 0; mt < 4; mt++)
                ldsm_x4(afr[mt], aOff + stoff + (uint32_t)(mt * 16 * ROWB + ks * 32));
            uint32_t bfr[2][4];
#pragma unroll
            for (int q = 0; q < 2; q++)
                ldsm_x4(bfr[q], bOff + stoff + (uint32_t)(q * 16 * ROWB + ks * 32));
#pragma unroll
            for (int mt = 0; mt < 4; mt++)
#pragma unroll
                for (int nt = 0; nt < 4; nt++)
                    mma_fp8(acc[mt][nt], afr[mt],
                            bfr[nt >> 1][nt & 1], bfr[nt >> 1][(nt & 1) + 2]);
        }
    }

    // ---- Fused epilogue: logits = acc * scale * (1-beta) / QSCALE^2 ----
    const float scale = __ldg(scale_p) * (1.0f - g_beta) / (QSCALE * QSCALE);
#pragma unroll
    for (int mt = 0; mt < 4; mt++)
#pragma unroll
        for (int nt = 0; nt < 4; nt++)
#pragma unroll
            for (int i = 0; i < 4; i++) acc[mt][nt][i] *= scale;

    // Calibration extraction (diag block: bx == by)
    if (bx == by) {
#pragma unroll
        for (int mt = 0; mt < 4; mt++)
#pragma unroll
            for (int nt = 0; nt < 4; nt++)
#pragma unroll
                for (int i = 0; i < 4; i++) {
                    int r_loc = wm * 64 + mt * 16 + ((i >> 1) << 3) + (lane >> 2);
                    int c_loc = wn * 32 + nt * 8 + ((lane & 3) << 1) + (i & 1);
                    if (c_loc == r_loc)
                        g_diag8[by * BM + r_loc] = acc[mt][nt][i];
                    if (c_loc == (r_loc ^ 1))
                        g_off81[by * BM + r_loc] = acc[mt][nt][i];
                }
    }

    float m = -INFINITY;
#pragma unroll
    for (int mt = 0; mt < 4; mt++)
#pragma unroll
        for (int nt = 0; nt < 4; nt++)
#pragma unroll
            for (int i = 0; i < 4; i++) m = fmaxf(m, acc[mt][nt][i]);
#pragma unroll
    for (int off = 16; off > 0; off >>= 1)
        m = fmaxf(m, __shfl_xor_sync(0xffffffffu, m, off));
    if (lane == 0) s_red[wid] = m;
    __syncthreads();
    float Mt = s_red[0];
#pragma unroll
    for (int w = 1; w < 8; w++) Mt = fmaxf(Mt, s_red[w]);

#pragma unroll
    for (int mt = 0; mt < 4; mt++)
#pragma unroll
        for (int nt = 0; nt < 4; nt++)
#pragma unroll
            for (int i = 0; i < 4; i++)
                acc[mt][nt][i] = __expf(acc[mt][nt][i] - Mt);

    // Row partial sums. Accum layout: reg i: row (i>>1)*8+(lane>>2),
    // col (lane&3)*2+(i&1), within each 16x8 sub-tile.
#pragma unroll
    for (int mt = 0; mt < 4; mt++)
#pragma unroll
        for (int half = 0; half < 2; half++) {
            float rs = 0.0f;
#pragma unroll
            for (int nt = 0; nt < 4; nt++)
                rs += acc[mt][nt][half * 2] + acc[mt][nt][half * 2 + 1];
            rs += __shfl_xor_sync(0xffffffffu, rs, 1);
            rs += __shfl_xor_sync(0xffffffffu, rs, 2);
            if ((lane & 3) == 0)
                s_rows[wn][wm * 64 + mt * 16 + half * 8 + (lane >> 2)] = rs;
        }

    // Col partial sums
#pragma unroll
    for (int nt = 0; nt < 4; nt++)
#pragma unroll
        for (int cc = 0; cc < 2; cc++) {
            float cs = 0.0f;
#pragma unroll
            for (int mt = 0; mt < 4; mt++)
                cs += acc[mt][nt][cc] + acc[mt][nt][cc + 2];
            cs += __shfl_xor_sync(0xffffffffu, cs, 4);
            cs += __shfl_xor_sync(0xffffffffu, cs, 8);
            cs += __shfl_xor_sync(0xffffffffu, cs, 16);
            if (lane < 4)
                s_cols[wm][wn * 32 + nt * 8 + (lane & 3) * 2 + cc] = cs;
        }
    __syncthreads();

    if (tid < 128) {
        float rs = s_rows[0][tid] + s_rows[1][tid] + s_rows[2][tid] + s_rows[3][tid];
        g_rowP[(size_t)bx * N + by * BM + tid] = make_float2(Mt, rs);
        float cs = s_cols[0][tid] + s_cols[1][tid];
        g_colP[(size_t)by * N + bx * BN + tid] = make_float2(Mt, cs);
    }
}

// ---------------------------------------------------------------------------
// Stats: accumulate sum exp(delta) over 2N calibration pairs (32 blocks).
// ---------------------------------------------------------------------------
__global__ void __launch_bounds__(256)
stats_kernel() {
    __shared__ float sm[8];
    const int tid = threadIdx.x;
    const int k = blockIdx.x * 256 + tid;
    float d0 = g_diag8[k] - g_diag[k];
    float d1 = g_off81[k] - g_offx1[k];
    float a1 = __expf(d0) + __expf(d1);
#pragma unroll
    for (int off = 16; off > 0; off >>= 1)
        a1 += __shfl_xor_sync(0xffffffffu, a1, off);
    if ((tid & 31) == 0) sm[tid >> 5] = a1;
    __syncthreads();
    if (tid == 0) {
        float t = 0;
#pragma unroll
        for (int w = 0; w < 8; w++) t += sm[w];
        atomicAdd(&g_m1sum, t);
    }
}

// ---------------------------------------------------------------------------
// Combine partials -> bias-corrected lse, subtract diag, reduce.
// Blocks 0..31: rows. Blocks 32..63: cols. 64 tiles each.
// ---------------------------------------------------------------------------
__global__ void reduce_kernel() {
    const bool rowdir = blockIdx.x < 32;
    const int i = (rowdir ? blockIdx.x : blockIdx.x - 32) * 256 + threadIdx.x;
    const float2* P = rowdir ? g_rowP : g_colP;

    const float logm1 = logf(g_m1sum / (2.0f * N));

    float m = -INFINITY, s = 0.0f;
    for (int t = 0; t < NT; t++) {
        float2 p = P[(size_t)t * N + i];
        float nm = fmaxf(m, p.x);
        s = s * __expf(m - nm) + p.y * __expf(p.x - nm);
        m = nm;
    }
    float lse = m + logf(s) - logm1;
    float v = lse - g_diag[i];

    __shared__ float sm[256];
    sm[threadIdx.x] = v;
    __syncthreads();
    for (int off = 128; off > 0; off >>= 1) {
        if (threadIdx.x < off) sm[threadIdx.x] += sm[threadIdx.x + off];
        __syncthreads();
    }
    if (threadIdx.x == 0) atomicAdd(&g_acc, (double)sm[0]);
}

__global__ void final_kernel(float* out) {
    out[0] = (float)(g_acc / (2.0 * (double)N));
}

// ---------------------------------------------------------------------------
extern "C" void kernel_launch(void* const* d_in, const int* in_sizes, int n_in,
                              void* d_out, int out_size) {
    const float* img   = (const float*)d_in[0];
    const float* txt   = (const float*)d_in[1];
    const float* scale = (const float*)d_in[2];
    float* out = (float*)d_out;

    cudaFuncSetAttribute(gemm_lse_mma, cudaFuncAttributeMaxDynamicSharedMemorySize, DSMEM_BYTES);

    init_kernel<<<1, 1>>>();
    convert_diag_kernel<<<N, 256>>>(img, txt, scale);
    beta_kernel<<<1, 1>>>();

    dim3 grid(NT, NT);  // 64 x 64
    gemm_lse_mma<<<grid, 256, DSMEM_BYTES>>>(scale);

    stats_kernel<<<32, 256>>>();
    reduce_kernel<<<64, 256>>>();
    final_kernel<<<1, 1>>>(out);
}